// round 1
// baseline (speedup 1.0000x reference)
#include <cuda_runtime.h>

// Problem constants (Modelev12: 2-layer LSTM, H=48, B=4096, T=512, F=64)
#define H      48
#define TOBS   512
#define FPRED  64
#define TTOT   (TOBS + FPRED)     // 576
#define BATCH  4096
#define MB     32                 // batch rows per CTA
#define NCTA   (BATCH / MB)       // 128
#define NTHR   256                // 8 warps -> 2 per SMSP (balanced)
#define HSTRIDE 112               // h-row stride (pad: 112 % 32 == 16 -> 2-way worst)

// shared memory layout (float offsets)
#define OFF_WT0 0                              // [48][192]  Whh0^T
#define OFF_WT1 9216                           // [96][192]  [Wih1|Whh1]^T
#define OFF_WI0 27648                          // [192]      Wih0 column
#define OFF_B0  27840                          // [192]      bih0+bhh0
#define OFF_B1  28032                          // [192]      bih1+bhh1
#define OFF_WL  28224                          // [48]       W_lin
#define OFF_HC  28272                          // [32][HSTRIDE]  h0 (0..47) | h1 (48..95)
#define OFF_XC  (OFF_HC + 32*HSTRIDE)          // [32]       current input per row
#define OFF_GT  (OFF_XC + 32)                  // [32][192]  gate pre-activations
#define SMEM_FLOATS (OFF_GT + 32*192)
#define SMEM_BYTES  (SMEM_FLOATS * 4)

__device__ __forceinline__ float fsig(float xv) {
    float e = __expf(-xv);
    return __fdividef(1.0f, 1.0f + e);
}
__device__ __forceinline__ float ftanh(float xv) {
    float a = fabsf(xv);
    float e = __expf(-2.0f * a);          // e <= 1, no overflow
    float r = __fdividef(1.0f - e, 1.0f + e);
    return copysignf(r, xv);
}

__global__ void __launch_bounds__(NTHR, 1) lstm576_kernel(
    const float* __restrict__ x,
    const float* __restrict__ wih0, const float* __restrict__ whh0,
    const float* __restrict__ bih0, const float* __restrict__ bhh0,
    const float* __restrict__ wih1, const float* __restrict__ whh1,
    const float* __restrict__ bih1, const float* __restrict__ bhh1,
    const float* __restrict__ wlin, const float* __restrict__ blin,
    float* __restrict__ out)
{
    extern __shared__ float sm[];
    float* WT0 = sm + OFF_WT0;
    float* WT1 = sm + OFF_WT1;
    float* WI0 = sm + OFF_WI0;
    float* B0s = sm + OFF_B0;
    float* B1s = sm + OFF_B1;
    float* WLs = sm + OFF_WL;
    float* HCs = sm + OFF_HC;
    float* XCs = sm + OFF_XC;
    float* GTs = sm + OFF_GT;

    const int tid = threadIdx.x;
    const int rg  = tid & 31;      // lane = row group (rows rg, rg+32, ..., rg+160)
    const int bgr = tid >> 5;      // warp = batch group (4 rows of the 32)
    const int bb0 = bgr * 4;
    const int gb0 = blockIdx.x * MB;

    // ---- stage weights (transposed: WT[k*192 + r] = W[r][k]), one-time ----
    for (int i = tid; i < 48 * 192; i += NTHR) {
        int k = i / 192, r = i - k * 192;
        WT0[i] = whh0[r * 48 + k];
    }
    for (int i = tid; i < 96 * 192; i += NTHR) {
        int k = i / 192, r = i - k * 192;
        WT1[i] = (k < 48) ? wih1[r * 48 + k] : whh1[r * 48 + (k - 48)];
    }
    for (int i = tid; i < 192; i += NTHR) {
        WI0[i] = wih0[i];                 // [192,1] column
        B0s[i] = bih0[i] + bhh0[i];
        B1s[i] = bih1[i] + bhh1[i];
    }
    if (tid < 48) WLs[tid] = wlin[tid];
    for (int i = tid; i < 32 * HSTRIDE; i += NTHR) HCs[i] = 0.0f;  // h0 = h1 = 0
    if (tid < MB) XCs[tid] = x[(size_t)(gb0 + tid) * TOBS];        // x[:,0]
    const float blv = blin[0];

    // activation ownership: element e = b*48 + j, thread owns e = tid + 256*i
    float c0r[6], c1r[6];
    int eb[6], ej[6];
#pragma unroll
    for (int i = 0; i < 6; i++) {
        c0r[i] = 0.0f; c1r[i] = 0.0f;
        int e = tid + NTHR * i;
        eb[i] = e / 48; ej[i] = e - 48 * eb[i];
    }
    __syncthreads();

    float acc[6][4];

    for (int t = 0; t < TTOT; t++) {
        // prefetch next observed input early (hides DRAM/L2 latency)
        float xnext = 0.0f;
        if (tid < MB && (t + 1) < TOBS)
            xnext = x[(size_t)(gb0 + tid) * TOBS + (t + 1)];

        // ================= layer 0 matvec: gates0 = Whh0 @ h0 + Wih0*x + b =================
        {
#pragma unroll
            for (int ri = 0; ri < 6; ri++) {
                float bsv = B0s[rg + 32 * ri];
                float wiv = WI0[rg + 32 * ri];
#pragma unroll
                for (int bi = 0; bi < 4; bi++)
                    acc[ri][bi] = fmaf(wiv, XCs[bb0 + bi], bsv);
            }
#pragma unroll 4
            for (int kt = 0; kt < 48; kt += 4) {
                float4 hv[4];
#pragma unroll
                for (int bi = 0; bi < 4; bi++)
                    hv[bi] = *(const float4*)(HCs + (bb0 + bi) * HSTRIDE + kt);
#pragma unroll
                for (int d = 0; d < 4; d++) {
                    float w[6];
#pragma unroll
                    for (int ri = 0; ri < 6; ri++)
                        w[ri] = WT0[(kt + d) * 192 + rg + 32 * ri];
#pragma unroll
                    for (int bi = 0; bi < 4; bi++) {
                        float hvv = (d == 0) ? hv[bi].x : (d == 1) ? hv[bi].y
                                  : (d == 2) ? hv[bi].z : hv[bi].w;
#pragma unroll
                        for (int ri = 0; ri < 6; ri++)
                            acc[ri][bi] = fmaf(w[ri], hvv, acc[ri][bi]);
                    }
                }
            }
#pragma unroll
            for (int ri = 0; ri < 6; ri++)
#pragma unroll
                for (int bi = 0; bi < 4; bi++)
                    GTs[(bb0 + bi) * 192 + rg + 32 * ri] = acc[ri][bi];
        }
        __syncthreads();

        // ---- layer 0 activations: c,h update (c in registers) ----
#pragma unroll
        for (int i = 0; i < 6; i++) {
            const float* g4 = GTs + eb[i] * 192 + ej[i];
            float ii = fsig(g4[0]);
            float ff = fsig(g4[48]);
            float gg = ftanh(g4[96]);
            float oo = fsig(g4[144]);
            float c  = fmaf(ff, c0r[i], ii * gg);
            c0r[i]   = c;
            HCs[eb[i] * HSTRIDE + ej[i]] = oo * ftanh(c);   // h0_new
        }
        __syncthreads();

        // ================= layer 1 matvec: gates1 = [Wih1|Whh1] @ [h0_new; h1] + b =================
        {
#pragma unroll
            for (int ri = 0; ri < 6; ri++) {
                float bsv = B1s[rg + 32 * ri];
#pragma unroll
                for (int bi = 0; bi < 4; bi++)
                    acc[ri][bi] = bsv;
            }
#pragma unroll 4
            for (int kt = 0; kt < 96; kt += 4) {
                float4 hv[4];
#pragma unroll
                for (int bi = 0; bi < 4; bi++)
                    hv[bi] = *(const float4*)(HCs + (bb0 + bi) * HSTRIDE + kt);
#pragma unroll
                for (int d = 0; d < 4; d++) {
                    float w[6];
#pragma unroll
                    for (int ri = 0; ri < 6; ri++)
                        w[ri] = WT1[(kt + d) * 192 + rg + 32 * ri];
#pragma unroll
                    for (int bi = 0; bi < 4; bi++) {
                        float hvv = (d == 0) ? hv[bi].x : (d == 1) ? hv[bi].y
                                  : (d == 2) ? hv[bi].z : hv[bi].w;
#pragma unroll
                        for (int ri = 0; ri < 6; ri++)
                            acc[ri][bi] = fmaf(w[ri], hvv, acc[ri][bi]);
                    }
                }
            }
#pragma unroll
            for (int ri = 0; ri < 6; ri++)
#pragma unroll
                for (int bi = 0; bi < 4; bi++)
                    GTs[(bb0 + bi) * 192 + rg + 32 * ri] = acc[ri][bi];
        }
        __syncthreads();

        // ---- layer 1 activations ----
#pragma unroll
        for (int i = 0; i < 6; i++) {
            const float* g4 = GTs + eb[i] * 192 + ej[i];
            float ii = fsig(g4[0]);
            float ff = fsig(g4[48]);
            float gg = ftanh(g4[96]);
            float oo = fsig(g4[144]);
            float c  = fmaf(ff, c1r[i], ii * gg);
            c1r[i]   = c;
            HCs[eb[i] * HSTRIDE + 48 + ej[i]] = oo * ftanh(c); // h1_new
        }
        __syncthreads();

        // ---- output head + next-step input ----
        if (tid < MB) {
            const float* h1 = HCs + tid * HSTRIDE + 48;
            float s0 = 0.f, s1 = 0.f, s2 = 0.f, s3 = 0.f;
#pragma unroll
            for (int k = 0; k < 48; k += 4) {
                float4 hq = *(const float4*)(h1 + k);
                float4 wq = *(const float4*)(WLs + k);
                s0 = fmaf(hq.x, wq.x, s0);
                s1 = fmaf(hq.y, wq.y, s1);
                s2 = fmaf(hq.z, wq.z, s2);
                s3 = fmaf(hq.w, wq.w, s3);
            }
            float s = (s0 + s1) + (s2 + s3) + blv;
            out[(size_t)(gb0 + tid) * TTOT + t] = s;
            XCs[tid] = ((t + 1) < TOBS) ? xnext : s;   // teacher forcing -> autoregressive
        }
        __syncthreads();
    }
}

extern "C" void kernel_launch(void* const* d_in, const int* in_sizes, int n_in,
                              void* d_out, int out_size)
{
    (void)in_sizes; (void)n_in; (void)out_size;
    const float* x    = (const float*)d_in[0];
    const float* wih0 = (const float*)d_in[1];
    const float* whh0 = (const float*)d_in[2];
    const float* bih0 = (const float*)d_in[3];
    const float* bhh0 = (const float*)d_in[4];
    const float* wih1 = (const float*)d_in[5];
    const float* whh1 = (const float*)d_in[6];
    const float* bih1 = (const float*)d_in[7];
    const float* bhh1 = (const float*)d_in[8];
    const float* wlin = (const float*)d_in[9];
    const float* blin = (const float*)d_in[10];
    float* out = (float*)d_out;

    cudaFuncSetAttribute(lstm576_kernel,
                         cudaFuncAttributeMaxDynamicSharedMemorySize, SMEM_BYTES);
    lstm576_kernel<<<NCTA, NTHR, SMEM_BYTES>>>(
        x, wih0, whh0, bih0, bhh0, wih1, whh1, bih1, bhh1, wlin, blin, out);
}